// round 5
// baseline (speedup 1.0000x reference)
#include <cuda_runtime.h>

#define BATCHN 256
#define SEQN   1024
#define HIDN   200
#define VOCABN 33

#define NCPG  50            // col groups of 4
#define NCHK  10            // i-chunks of 20
#define NI    20
#define NWRK  500           // GEMV workers (tid<500)
#define WREG  512           // worker region = warps 0..15
#define NFIN  64            // finalize threads (warps 16,17)
#define NLOGW 396           // worker-logits threads
#define TPB   576

__device__ float d_E2[VOCABN * HIDN];
__device__ int   d_x_is32;

__global__ void prep_kernel(const float* __restrict__ emb,
                            const float* __restrict__ We,
                            const int* __restrict__ x32) {
    int v = blockIdx.x, j = threadIdx.x;
    if (v == 0 && j == 0) {
        int is32 = 0;
        for (int i = 0; i < 128; i++)
            if (x32[2 * i + 1] != 0) is32 = 1;
        d_x_is32 = is32;
    }
    float acc = 0.f;
#pragma unroll 8
    for (int e = 0; e < HIDN; e++)
        acc += emb[v * HIDN + e] * We[e * HIDN + j];
    d_E2[v * HIDN + j] = acc;
}

struct __align__(16) Smem {
    float4 hdup[2][HIDN];            // [par][i] = {h0,h0,h1,h1}
    float4 part[NCHK][2][NCPG];      // GEMV partials
    float  hrow[2][2][HIDN];         // [par][row][i]
    float  e2[VOCABN * HIDN];
    float2 wot2[VOCABN * 101];       // [v][k] = {Wo[2k][v],Wo[2k+1][v]}
    float  lp[2][6][2][VOCABN];      // logits partials [par][q][row][v]
    int    xi[2][SEQN];
};

union F2U { unsigned long long u; float2 f2; };

__device__ __forceinline__ void fma2(unsigned long long& d,
                                     unsigned long long a,
                                     unsigned long long b) {
    asm("fma.rn.f32x2 %0, %1, %2, %0;" : "+l"(d) : "l"(a), "l"(b));
}
__device__ __forceinline__ float fast_tanh(float x) {
    float e = __expf(2.0f * x);
    return 1.0f - __fdividef(2.0f, e + 1.0f);
}
__device__ __forceinline__ void bar_arrive(int id) {
    asm volatile("bar.arrive %0, %1;" :: "r"(id), "r"(TPB) : "memory");
}
__device__ __forceinline__ void bar_sync(int id) {
    asm volatile("bar.sync %0, %1;" :: "r"(id), "r"(TPB) : "memory");
}

extern __shared__ unsigned char smem_raw[];

__constant__ int c_lstart[6] = {0, 34, 68, 102, 136, 168};
__constant__ int c_liter[6]  = {17, 17, 17, 17, 16, 16};

__global__ void __launch_bounds__(TPB, 1)
scan_kernel(const void* __restrict__ xv,
            const float* __restrict__ hidden,
            const float* __restrict__ Wh,
            const float* __restrict__ Wo,
            float* __restrict__ out_logits,
            float* __restrict__ out_hidden,
            int write_h) {
    Smem& s = *reinterpret_cast<Smem*>(smem_raw);
    const int tid = threadIdx.x;
    const int b0  = blockIdx.x * 2;

    // ---- setup ----
    for (int k = tid; k < VOCABN * HIDN; k += TPB) s.e2[k] = d_E2[k];
    for (int k = tid; k < VOCABN * 100; k += TPB) {
        int v = k / 100, i = k % 100;
        s.wot2[v * 101 + i] = make_float2(Wo[(2 * i) * VOCABN + v],
                                          Wo[(2 * i + 1) * VOCABN + v]);
    }
    {
        const int is32 = d_x_is32;
        const int* __restrict__ x32 = (const int*)xv;
        const long long* __restrict__ x64 = (const long long*)xv;
        for (int k = tid; k < 2 * SEQN; k += TPB) {
            int r = k >> 10, t = k & (SEQN - 1);
            long long idx = is32 ? (long long)x32[(size_t)(b0 + r) * SEQN + t]
                                 : x64[(size_t)(b0 + r) * SEQN + t];
            s.xi[r][t] = (int)idx;
        }
    }
    for (int j = tid; j < HIDN; j += TPB) {
        float a = hidden[(size_t)b0 * HIDN + j];
        float b = hidden[(size_t)(b0 + 1) * HIDN + j];
        s.hdup[0][j] = make_float4(a, a, b, b);
    }

    // ---- worker W slice: 4 cols x 20 i -> 80 regs ----
    const int cpg = tid % NCPG;
    const int ch  = tid / NCPG;
    const int i0  = ch * NI;
    unsigned long long w0r[NI], w1r[NI];
    if (tid < NWRK) {
        const float* wp = Wh + (size_t)i0 * HIDN + 4 * cpg;
#pragma unroll
        for (int ii = 0; ii < NI; ii++) {
            w0r[ii] = *reinterpret_cast<const unsigned long long*>(wp + (size_t)ii * HIDN);
            w1r[ii] = *reinterpret_cast<const unsigned long long*>(wp + (size_t)ii * HIDN + 2);
        }
    }

    // worker-logits mapping: tid<396 -> (v, row, qchunk)
    const int lv = tid % VOCABN;
    const int lg = tid / VOCABN;       // 0..11
    const int lr = lg & 1;
    const int lq = lg >> 1;            // 0..5

    // finalize mapping: fk = tid-512: row = fk&1, colbase = fk>>1
    const int fk = tid - WREG;
    const int frow = fk & 1;
    const int fcb  = fk >> 1;

    __syncthreads();

    for (int t = 0; t <= SEQN + 1; t++) {
        if (tid < WREG) {
            // ================= worker region =================
            if (tid < NWRK && t < SEQN) {
                const int rb = t & 1;
                F2U a00, a01, a10, a11;
                a00.u = a01.u = a10.u = a11.u = 0ull;
                const ulonglong2* hp =
                    reinterpret_cast<const ulonglong2*>(&s.hdup[rb][i0]);
#pragma unroll
                for (int ii = 0; ii < NI; ii++) {
                    ulonglong2 hd = hp[ii];
                    fma2(a00.u, w0r[ii], hd.x);
                    fma2(a01.u, w1r[ii], hd.x);
                    fma2(a10.u, w0r[ii], hd.y);
                    fma2(a11.u, w1r[ii], hd.y);
                }
                s.part[ch][0][cpg] = make_float4(a00.f2.x, a00.f2.y, a01.f2.x, a01.f2.y);
                s.part[ch][1][cpg] = make_float4(a10.f2.x, a10.f2.y, a11.f2.x, a11.f2.y);
            }
            bar_arrive(1);
            // logits partials for h_{t-1} (parity t&1), overlapped with finalize
            if (tid < NLOGW && t >= 1 && t <= SEQN) {
                const int p  = t & 1;
                const int li0 = c_lstart[lq];
                const int nit = c_liter[lq];
                F2U acc; acc.u = 0ull;
                const unsigned long long* wp2 = reinterpret_cast<const unsigned long long*>(
                    &s.wot2[lv * 101 + (li0 >> 1)]);
                const unsigned long long* hp2 = reinterpret_cast<const unsigned long long*>(
                    &s.hrow[p][lr][li0]);
                for (int k = 0; k < nit; k++)
                    fma2(acc.u, wp2[k], hp2[k]);
                s.lp[p][lq][lr][lv] = acc.f2.x + acc.f2.y;
            }
            bar_sync(2);
        } else {
            // ================= finalize region =================
            bar_sync(1);
            if (t < SEQN) {
                const int wp = (t & 1) ^ 1;
                const int xi = s.xi[frow][t];
                const float* pb = reinterpret_cast<const float*>(s.part);
#pragma unroll 4
                for (int j = fcb; j < HIDN; j += 32) {
                    float sum = 0.f;
#pragma unroll
                    for (int c = 0; c < NCHK; c++)
                        sum += pb[((c * 2 + frow) * NCPG + (j >> 2)) * 4 + (j & 3)];
                    float h = fast_tanh(sum + s.e2[xi * HIDN + j]);
                    F2U hh; hh.f2 = make_float2(h, h);
                    *reinterpret_cast<unsigned long long*>(
                        reinterpret_cast<char*>(&s.hdup[wp][j]) + frow * 8) = hh.u;
                    s.hrow[wp][frow][j] = h;
                }
            }
            if (t >= 2) {
                const int pf = (t - 1) & 1;     // lp parity written at step t-1
                const int trow = t - 2;
#pragma unroll
                for (int rep = 0; rep < 2; rep++) {
                    int task = fk + rep * NFIN;
                    if (task < 2 * VOCABN) {
                        int v = task % VOCABN, r = task / VOCABN;
                        float L = 0.f;
#pragma unroll
                        for (int q = 0; q < 6; q++) L += s.lp[pf][q][r][v];
                        out_logits[(size_t)(b0 + r) * SEQN * VOCABN
                                   + (size_t)trow * VOCABN + v] = L;
                    }
                }
            }
            bar_arrive(2);
        }
    }

    // ---- final hidden: h_{SEQN-1} is at parity ((SEQN-1)+1)&1 = 0 ----
    if (write_h && tid < 2 * HIDN) {
        const int fc = tid % HIDN, fr2 = tid / HIDN;
        out_hidden[(size_t)(b0 + fr2) * HIDN + fc] = s.hrow[0][fr2][fc];
    }
}

extern "C" void kernel_launch(void* const* d_in, const int* in_sizes, int n_in,
                              void* d_out, int out_size) {
    const void*  x      = d_in[0];
    const float* hidden = (const float*)d_in[1];
    const float* emb    = (const float*)d_in[2];
    const float* We     = (const float*)d_in[3];
    const float* Wh     = (const float*)d_in[4];
    const float* Wo     = (const float*)d_in[5];

    float* logits = (float*)d_out;
    const long long LOGITS_ELEMS = (long long)BATCHN * SEQN * VOCABN;
    int write_h = (out_size >= (int)(LOGITS_ELEMS + BATCHN * HIDN));
    float* outh = logits + LOGITS_ELEMS;

    prep_kernel<<<VOCABN, HIDN>>>(emb, We, (const int*)x);

    cudaFuncSetAttribute((const void*)scan_kernel,
                         cudaFuncAttributeMaxDynamicSharedMemorySize,
                         (int)sizeof(Smem));
    scan_kernel<<<BATCHN / 2, TPB, sizeof(Smem)>>>(
        x, hidden, Wh, Wo, logits, outh, write_h);
}

// round 6
// speedup vs baseline: 3.1133x; 3.1133x over previous
#include <cuda_runtime.h>

#define BATCHN 256
#define SEQN   1024
#define HIDN   200
#define VOCABN 33

#define NCPG  50            // col groups of 4: 50*4 = 200
#define NCHK  10            // i-chunks of 20
#define NI    20
#define NWRK  500
#define TPB   512

#define WOPW  36            // padded W_o row (33 -> 36)
#define GTPB  256           // logits GEMM block
#define GROWS 2             // rows per GEMM thread

__device__ float d_E2[VOCABN * HIDN];
__device__ float d_wop[HIDN * WOPW];
__device__ int   d_x_is32;
__device__ float d_H[(size_t)BATCHN * SEQN * HIDN];   // 210MB scratch

union F2U { unsigned long long u; float2 f2; };

__device__ __forceinline__ void fma2(unsigned long long& d,
                                     unsigned long long a,
                                     unsigned long long b) {
    asm("fma.rn.f32x2 %0, %1, %2, %0;" : "+l"(d) : "l"(a), "l"(b));
}
__device__ __forceinline__ unsigned long long pack2(float x) {
    F2U r; r.f2 = make_float2(x, x); return r.u;
}
__device__ __forceinline__ float fast_tanh(float x) {
    float e = __expf(2.0f * x);
    return 1.0f - __fdividef(2.0f, e + 1.0f);
}

// ---------------------------------------------------------------------------
__global__ void prep_kernel(const float* __restrict__ emb,
                            const float* __restrict__ We,
                            const int* __restrict__ x32) {
    int v = blockIdx.x, j = threadIdx.x;
    if (v == 0 && j == 0) {
        int is32 = 0;
        for (int i = 0; i < 128; i++)
            if (x32[2 * i + 1] != 0) is32 = 1;
        d_x_is32 = is32;
    }
    float acc = 0.f;
#pragma unroll 8
    for (int e = 0; e < HIDN; e++)
        acc += emb[v * HIDN + e] * We[e * HIDN + j];
    d_E2[v * HIDN + j] = acc;
}

__global__ void prep2_kernel(const float* __restrict__ Wo) {
    int k = blockIdx.x * blockDim.x + threadIdx.x;
    if (k < HIDN * WOPW) {
        int i = k / WOPW, v = k % WOPW;
        d_wop[k] = (v < VOCABN) ? Wo[i * VOCABN + v] : 0.f;
    }
}

// ---------------------------------------------------------------------------
// Scan: recurrence only. Balanced phases, h rows streamed to d_H (GMEM).
// ---------------------------------------------------------------------------
struct __align__(16) Smem {
    float4 hdup[HIDN];               // {h0,h0,h1,h1} per column
    float4 part[NCHK][2][NCPG];      // GEMV partials
    float  e2[VOCABN * HIDN];
    int    xi[2][SEQN];
};

extern __shared__ unsigned char smem_raw[];

__global__ void __launch_bounds__(TPB, 1)
scan_kernel(const void* __restrict__ xv,
            const float* __restrict__ hidden,
            const float* __restrict__ Wh,
            float* __restrict__ out_hidden,
            int write_h) {
    Smem& s = *reinterpret_cast<Smem*>(smem_raw);
    const int tid = threadIdx.x;
    const int b0  = blockIdx.x * 2;

    // ---- setup ----
    for (int k = tid; k < VOCABN * HIDN; k += TPB) s.e2[k] = d_E2[k];
    {
        const int is32 = d_x_is32;
        const int* __restrict__ x32 = (const int*)xv;
        const long long* __restrict__ x64 = (const long long*)xv;
        for (int k = tid; k < 2 * SEQN; k += TPB) {
            int r = k >> 10, t = k & (SEQN - 1);
            long long idx = is32 ? (long long)x32[(size_t)(b0 + r) * SEQN + t]
                                 : x64[(size_t)(b0 + r) * SEQN + t];
            s.xi[r][t] = (int)idx;
        }
    }
    for (int j = tid; j < HIDN; j += TPB) {
        float a = hidden[(size_t)b0 * HIDN + j];
        float b = hidden[(size_t)(b0 + 1) * HIDN + j];
        s.hdup[j] = make_float4(a, a, b, b);
    }

    // ---- worker W_h slice: 4 cols x 20 i -> 80 regs ----
    const int cpg = tid % NCPG;
    const int ch  = tid / NCPG;
    const int i0  = ch * NI;
    unsigned long long w0r[NI], w1r[NI];
    if (tid < NWRK) {
        const float* wp = Wh + (size_t)i0 * HIDN + 4 * cpg;
#pragma unroll
        for (int ii = 0; ii < NI; ii++) {
            w0r[ii] = *reinterpret_cast<const unsigned long long*>(wp + (size_t)ii * HIDN);
            w1r[ii] = *reinterpret_cast<const unsigned long long*>(wp + (size_t)ii * HIDN + 2);
        }
    }

    // finalize mapping: tid<400 -> (fc, fr), consecutive fc => coalesced
    const int fc = tid % HIDN;
    const int fr = tid / HIDN;

    __syncthreads();

    for (int t = 0; t < SEQN; t++) {
        // ---- Phase 1: GEMV partials ----
        if (tid < NWRK) {
            F2U a00, a01, a10, a11;
            a00.u = a01.u = a10.u = a11.u = 0ull;
            const ulonglong2* hp =
                reinterpret_cast<const ulonglong2*>(&s.hdup[i0]);
#pragma unroll
            for (int ii = 0; ii < NI; ii++) {
                ulonglong2 hd = hp[ii];
                fma2(a00.u, w0r[ii], hd.x);
                fma2(a01.u, w1r[ii], hd.x);
                fma2(a10.u, w0r[ii], hd.y);
                fma2(a11.u, w1r[ii], hd.y);
            }
            s.part[ch][0][cpg] = make_float4(a00.f2.x, a00.f2.y, a01.f2.x, a01.f2.y);
            s.part[ch][1][cpg] = make_float4(a10.f2.x, a10.f2.y, a11.f2.x, a11.f2.y);
        }
        __syncthreads();

        // ---- Phase 2: finalize h_t, stream to GMEM ----
        if (tid < 2 * HIDN) {
            const float* pb = reinterpret_cast<const float*>(s.part);
            float sum = 0.f;
#pragma unroll
            for (int c = 0; c < NCHK; c++)
                sum += pb[((c * 2 + fr) * NCPG + (fc >> 2)) * 4 + (fc & 3)];
            const int xi = s.xi[fr][t];
            float h = fast_tanh(sum + s.e2[xi * HIDN + fc]);
            F2U hh; hh.f2 = make_float2(h, h);
            *reinterpret_cast<unsigned long long*>(
                reinterpret_cast<char*>(&s.hdup[fc]) + fr * 8) = hh.u;
            d_H[((size_t)(b0 + fr) * SEQN + t) * HIDN + fc] = h;
            if (write_h && t == SEQN - 1)
                out_hidden[(size_t)(b0 + fr) * HIDN + fc] = h;
        }
        __syncthreads();
    }
}

// ---------------------------------------------------------------------------
// Logits GEMM: out[row][v] = sum_i H[row][i] * Wo[i][v];  2 rows/thread, f32x2.
// ---------------------------------------------------------------------------
__global__ void __launch_bounds__(GTPB, 1)
logits_kernel(float* __restrict__ out) {
    __shared__ float wop_s[HIDN * WOPW];   // 28.8KB
    const int tid = threadIdx.x;
    for (int k = tid; k < HIDN * WOPW; k += GTPB) wop_s[k] = d_wop[k];
    __syncthreads();

    const size_t row0 = (size_t)blockIdx.x * (GTPB * GROWS) + tid;
    const size_t row1 = row0 + GTPB;

    F2U acc0[17], acc1[17];
#pragma unroll
    for (int p = 0; p < 17; p++) { acc0[p].u = 0ull; acc1[p].u = 0ull; }

    const float4* h0p = reinterpret_cast<const float4*>(&d_H[row0 * HIDN]);
    const float4* h1p = reinterpret_cast<const float4*>(&d_H[row1 * HIDN]);

#pragma unroll 2
    for (int ib = 0; ib < HIDN / 4; ib++) {
        float4 h0 = h0p[ib];
        float4 h1 = h1p[ib];
        const float he0[4] = {h0.x, h0.y, h0.z, h0.w};
        const float he1[4] = {h1.x, h1.y, h1.z, h1.w};
#pragma unroll
        for (int e = 0; e < 4; e++) {
            const int i = ib * 4 + e;
            const unsigned long long hd0 = pack2(he0[e]);
            const unsigned long long hd1 = pack2(he1[e]);
            // 8 x LDS.128 (2 v-pairs each) + 1 x LDS.64, all broadcast
            const ulonglong2* wp2 =
                reinterpret_cast<const ulonglong2*>(&wop_s[i * WOPW]);
#pragma unroll
            for (int q = 0; q < 8; q++) {
                ulonglong2 w = wp2[q];
                fma2(acc0[2 * q].u,     w.x, hd0);
                fma2(acc0[2 * q + 1].u, w.y, hd0);
                fma2(acc1[2 * q].u,     w.x, hd1);
                fma2(acc1[2 * q + 1].u, w.y, hd1);
            }
            unsigned long long wl =
                *reinterpret_cast<const unsigned long long*>(&wop_s[i * WOPW + 32]);
            fma2(acc0[16].u, wl, hd0);
            fma2(acc1[16].u, wl, hd1);
        }
    }

    float* o0 = out + row0 * VOCABN;
    float* o1 = out + row1 * VOCABN;
#pragma unroll
    for (int p = 0; p < 16; p++) {
        o0[2 * p] = acc0[p].f2.x;  o0[2 * p + 1] = acc0[p].f2.y;
        o1[2 * p] = acc1[p].f2.x;  o1[2 * p + 1] = acc1[p].f2.y;
    }
    o0[32] = acc0[16].f2.x;
    o1[32] = acc1[16].f2.x;
}

// ---------------------------------------------------------------------------
extern "C" void kernel_launch(void* const* d_in, const int* in_sizes, int n_in,
                              void* d_out, int out_size) {
    const void*  x      = d_in[0];
    const float* hidden = (const float*)d_in[1];
    const float* emb    = (const float*)d_in[2];
    const float* We     = (const float*)d_in[3];
    const float* Wh     = (const float*)d_in[4];
    const float* Wo     = (const float*)d_in[5];

    float* logits = (float*)d_out;
    const long long LOGITS_ELEMS = (long long)BATCHN * SEQN * VOCABN;
    int write_h = (out_size >= (int)(LOGITS_ELEMS + BATCHN * HIDN));
    float* outh = logits + LOGITS_ELEMS;

    prep_kernel<<<VOCABN, HIDN>>>(emb, We, (const int*)x);
    prep2_kernel<<<(HIDN * WOPW + 255) / 256, 256>>>(Wo);

    cudaFuncSetAttribute((const void*)scan_kernel,
                         cudaFuncAttributeMaxDynamicSharedMemorySize,
                         (int)sizeof(Smem));
    scan_kernel<<<BATCHN / 2, TPB, sizeof(Smem)>>>(x, hidden, Wh, outh, write_h);

    logits_kernel<<<(BATCHN * SEQN) / (GTPB * GROWS), GTPB>>>(logits);
}

// round 7
// speedup vs baseline: 3.1430x; 1.0095x over previous
#include <cuda_runtime.h>

#define BATCHN 256
#define SEQN   1024
#define HIDN   200
#define VOCABN 33

#define NCPG  50            // col groups of 4: 50*4 = 200
#define NCHK  10            // i-chunks of 20
#define NI    20
#define NWRK  500
#define TPB   512

#define WOPW  36            // padded W_o row (33 -> 36)
#define GTPB  256           // logits GEMM block

__device__ float d_E2[VOCABN * HIDN];
__device__ float d_wop[HIDN * WOPW];
__device__ int   d_x_is32;
__device__ float d_H[(size_t)BATCHN * SEQN * HIDN];   // 210MB scratch

union F2U { unsigned long long u; float2 f2; };

__device__ __forceinline__ void fma2(unsigned long long& d,
                                     unsigned long long a,
                                     unsigned long long b) {
    asm("fma.rn.f32x2 %0, %1, %2, %0;" : "+l"(d) : "l"(a), "l"(b));
}
__device__ __forceinline__ unsigned long long pack2(float x) {
    F2U r; r.f2 = make_float2(x, x); return r.u;
}
__device__ __forceinline__ float fast_tanh(float x) {
    float e = __expf(2.0f * x);
    return 1.0f - __fdividef(2.0f, e + 1.0f);
}

// ---------------------------------------------------------------------------
__global__ void prep_kernel(const float* __restrict__ emb,
                            const float* __restrict__ We,
                            const int* __restrict__ x32) {
    int v = blockIdx.x, j = threadIdx.x;
    if (v == 0 && j == 0) {
        int is32 = 0;
        for (int i = 0; i < 128; i++)
            if (x32[2 * i + 1] != 0) is32 = 1;
        d_x_is32 = is32;
    }
    float acc = 0.f;
#pragma unroll 8
    for (int e = 0; e < HIDN; e++)
        acc += emb[v * HIDN + e] * We[e * HIDN + j];
    d_E2[v * HIDN + j] = acc;
}

__global__ void prep2_kernel(const float* __restrict__ Wo) {
    int k = blockIdx.x * blockDim.x + threadIdx.x;
    if (k < HIDN * WOPW) {
        int i = k / WOPW, v = k % WOPW;
        d_wop[k] = (v < VOCABN) ? Wo[i * VOCABN + v] : 0.f;
    }
}

// ---------------------------------------------------------------------------
// Scan: recurrence only (unchanged from R6 win).
// ---------------------------------------------------------------------------
struct __align__(16) Smem {
    float4 hdup[HIDN];               // {h0,h0,h1,h1} per column
    float4 part[NCHK][2][NCPG];      // GEMV partials
    float  e2[VOCABN * HIDN];
    int    xi[2][SEQN];
};

extern __shared__ unsigned char smem_raw[];

__global__ void __launch_bounds__(TPB, 1)
scan_kernel(const void* __restrict__ xv,
            const float* __restrict__ hidden,
            const float* __restrict__ Wh,
            float* __restrict__ out_hidden,
            int write_h) {
    Smem& s = *reinterpret_cast<Smem*>(smem_raw);
    const int tid = threadIdx.x;
    const int b0  = blockIdx.x * 2;

    for (int k = tid; k < VOCABN * HIDN; k += TPB) s.e2[k] = d_E2[k];
    {
        const int is32 = d_x_is32;
        const int* __restrict__ x32 = (const int*)xv;
        const long long* __restrict__ x64 = (const long long*)xv;
        for (int k = tid; k < 2 * SEQN; k += TPB) {
            int r = k >> 10, t = k & (SEQN - 1);
            long long idx = is32 ? (long long)x32[(size_t)(b0 + r) * SEQN + t]
                                 : x64[(size_t)(b0 + r) * SEQN + t];
            s.xi[r][t] = (int)idx;
        }
    }
    for (int j = tid; j < HIDN; j += TPB) {
        float a = hidden[(size_t)b0 * HIDN + j];
        float b = hidden[(size_t)(b0 + 1) * HIDN + j];
        s.hdup[j] = make_float4(a, a, b, b);
    }

    const int cpg = tid % NCPG;
    const int ch  = tid / NCPG;
    const int i0  = ch * NI;
    unsigned long long w0r[NI], w1r[NI];
    if (tid < NWRK) {
        const float* wp = Wh + (size_t)i0 * HIDN + 4 * cpg;
#pragma unroll
        for (int ii = 0; ii < NI; ii++) {
            w0r[ii] = *reinterpret_cast<const unsigned long long*>(wp + (size_t)ii * HIDN);
            w1r[ii] = *reinterpret_cast<const unsigned long long*>(wp + (size_t)ii * HIDN + 2);
        }
    }

    const int fc = tid % HIDN;
    const int fr = tid / HIDN;

    __syncthreads();

    for (int t = 0; t < SEQN; t++) {
        if (tid < NWRK) {
            F2U a00, a01, a10, a11;
            a00.u = a01.u = a10.u = a11.u = 0ull;
            const ulonglong2* hp =
                reinterpret_cast<const ulonglong2*>(&s.hdup[i0]);
#pragma unroll
            for (int ii = 0; ii < NI; ii++) {
                ulonglong2 hd = hp[ii];
                fma2(a00.u, w0r[ii], hd.x);
                fma2(a01.u, w1r[ii], hd.x);
                fma2(a10.u, w0r[ii], hd.y);
                fma2(a11.u, w1r[ii], hd.y);
            }
            s.part[ch][0][cpg] = make_float4(a00.f2.x, a00.f2.y, a01.f2.x, a01.f2.y);
            s.part[ch][1][cpg] = make_float4(a10.f2.x, a10.f2.y, a11.f2.x, a11.f2.y);
        }
        __syncthreads();

        if (tid < 2 * HIDN) {
            const float* pb = reinterpret_cast<const float*>(s.part);
            float sum = 0.f;
#pragma unroll
            for (int c = 0; c < NCHK; c++)
                sum += pb[((c * 2 + fr) * NCPG + (fc >> 2)) * 4 + (fc & 3)];
            const int xi = s.xi[fr][t];
            float h = fast_tanh(sum + s.e2[xi * HIDN + fc]);
            F2U hh; hh.f2 = make_float2(h, h);
            *reinterpret_cast<unsigned long long*>(
                reinterpret_cast<char*>(&s.hdup[fc]) + fr * 8) = hh.u;
            d_H[((size_t)(b0 + fr) * SEQN + t) * HIDN + fc] = h;
            if (write_h && t == SEQN - 1)
                out_hidden[(size_t)(b0 + fr) * HIDN + fc] = h;
        }
        __syncthreads();
    }
}

// ---------------------------------------------------------------------------
// Logits GEMM v2: 1 row/thread, 3 blocks/SM for latency hiding.
// ---------------------------------------------------------------------------
__global__ void __launch_bounds__(GTPB, 3)
logits_kernel(float* __restrict__ out) {
    __shared__ float wop_s[HIDN * WOPW];   // 28.8KB
    const int tid = threadIdx.x;
    for (int k = tid; k < HIDN * WOPW; k += GTPB) wop_s[k] = d_wop[k];
    __syncthreads();

    const size_t row = (size_t)blockIdx.x * GTPB + tid;

    F2U acc[17];
#pragma unroll
    for (int p = 0; p < 17; p++) acc[p].u = 0ull;

    const float4* hp = reinterpret_cast<const float4*>(&d_H[row * HIDN]);

#pragma unroll 2
    for (int ib = 0; ib < HIDN / 4; ib++) {
        float4 h4 = hp[ib];
        const float he[4] = {h4.x, h4.y, h4.z, h4.w};
#pragma unroll
        for (int e = 0; e < 4; e++) {
            const int i = ib * 4 + e;
            const unsigned long long hd = pack2(he[e]);
            const ulonglong2* wp2 =
                reinterpret_cast<const ulonglong2*>(&wop_s[i * WOPW]);
#pragma unroll
            for (int q = 0; q < 8; q++) {
                ulonglong2 w = wp2[q];
                fma2(acc[2 * q].u,     w.x, hd);
                fma2(acc[2 * q + 1].u, w.y, hd);
            }
            unsigned long long wl =
                *reinterpret_cast<const unsigned long long*>(&wop_s[i * WOPW + 32]);
            fma2(acc[16].u, wl, hd);
        }
    }

    float* o = out + row * VOCABN;
#pragma unroll
    for (int p = 0; p < 16; p++) {
        o[2 * p]     = acc[p].f2.x;
        o[2 * p + 1] = acc[p].f2.y;
    }
    o[32] = acc[16].f2.x;
}

// ---------------------------------------------------------------------------
extern "C" void kernel_launch(void* const* d_in, const int* in_sizes, int n_in,
                              void* d_out, int out_size) {
    const void*  x      = d_in[0];
    const float* hidden = (const float*)d_in[1];
    const float* emb    = (const float*)d_in[2];
    const float* We     = (const float*)d_in[3];
    const float* Wh     = (const float*)d_in[4];
    const float* Wo     = (const float*)d_in[5];

    float* logits = (float*)d_out;
    const long long LOGITS_ELEMS = (long long)BATCHN * SEQN * VOCABN;
    int write_h = (out_size >= (int)(LOGITS_ELEMS + BATCHN * HIDN));
    float* outh = logits + LOGITS_ELEMS;

    prep_kernel<<<VOCABN, HIDN>>>(emb, We, (const int*)x);
    prep2_kernel<<<(HIDN * WOPW + 255) / 256, 256>>>(Wo);

    cudaFuncSetAttribute((const void*)scan_kernel,
                         cudaFuncAttributeMaxDynamicSharedMemorySize,
                         (int)sizeof(Smem));
    scan_kernel<<<BATCHN / 2, TPB, sizeof(Smem)>>>(x, hidden, Wh, outh, write_h);

    logits_kernel<<<(BATCHN * SEQN) / GTPB, GTPB>>>(logits);
}